// round 11
// baseline (speedup 1.0000x reference)
#include <cuda_runtime.h>
#include <cuda_fp16.h>
#include <cstdint>

#define B_    8
#define N_    2048
#define F_    512
#define MTOT  (B_ * N_)          // 16384
#define NEGV  (-10000.0f)
#define SLOPE 0.2f
#define FULLM 0xFFFFFFFFu

// ---------------- device scratch (sanctioned static-array path) -------------
__device__ __half g_tHi[(size_t)MTOT * F_];
__device__ __half g_WHi[(size_t)F_ * F_];
__device__ __half g_hHi[(size_t)MTOT * F_];   // hidden fp16, row-major
__device__ float g_ws[F_], g_wd[F_];          // W @ a_src, W @ a_dst
__device__ float g_sbdb[2];                   // b.a_src, b.a_dst
__device__ float g_sv[MTOT], g_dv[MTOT];
__device__ __half g_PHi[(size_t)MTOT * N_];

// ---------------- base-target PTX helpers ------------------------------------
__device__ __forceinline__ uint32_t smem_u32(const void* p) {
    uint32_t a;
    asm("{ .reg .u64 t; cvta.to.shared.u64 t, %1; cvt.u32.u64 %0, t; }"
        : "=r"(a) : "l"(p));
    return a;
}
__device__ __forceinline__ void cp16(uint32_t dst, const void* src) {
    asm volatile("cp.async.cg.shared.global [%0], [%1], 16;" :: "r"(dst), "l"(src));
}
#define CP_COMMIT() asm volatile("cp.async.commit_group;" ::: "memory")
#define CP_WAIT(n)  asm volatile("cp.async.wait_group %0;" :: "n"(n) : "memory")

#define LDSM4(r0, r1, r2, r3, addr) \
    asm volatile("ldmatrix.sync.aligned.m8n8.x4.shared.b16 {%0,%1,%2,%3}, [%4];" \
                 : "=r"(r0), "=r"(r1), "=r"(r2), "=r"(r3) : "r"(addr))
#define LDSM4T(r0, r1, r2, r3, addr) \
    asm volatile("ldmatrix.sync.aligned.m8n8.x4.trans.shared.b16 {%0,%1,%2,%3}, [%4];" \
                 : "=r"(r0), "=r"(r1), "=r"(r2), "=r"(r3) : "r"(addr))

#define MMA(d, a, b) \
    asm volatile("mma.sync.aligned.m16n8k16.row.col.f32.f16.f16.f32 " \
                 "{%0,%1,%2,%3}, {%4,%5,%6,%7}, {%8,%9}, {%0,%1,%2,%3};" \
                 : "+f"((d)[0]), "+f"((d)[1]), "+f"((d)[2]), "+f"((d)[3]) \
                 : "r"((a)[0]), "r"((a)[1]), "r"((a)[2]), "r"((a)[3]), \
                   "r"((b)[0]), "r"((b)[1]))

// ---------------- SMEM layout -------------------------------------------------
#define A_PITCH_B 80
#define B_PITCH_B 272
#define SZ_A (128 * A_PITCH_B)            // 10240
#define SZ_B (32 * B_PITCH_B)             // 8704
#define STAGES 3
#define BUF_STRIDE (SZ_A + SZ_B)          // 18944
#define SMEM_BYTES (STAGES * BUF_STRIDE)  // 56832

// ---------------- 1-term fp16 GEMM (mma.sync), CTA 128x128x32 ----------------
// EXACT R7 kernel text (known-good codegen; do not refactor).
// C = Ahi * Bhi  (fp32 accumulate)
// MODE 0: hHi = fp16(C + bias)
// MODE 1: outF[row][512] = C  (fp32)
template<int MODE>
__global__ __launch_bounds__(256) void gemm_mma(
    const __half* __restrict__ Ahi, const __half* __restrict__ Bhi,
    int lda, int ldb, int K, int AZ, int BZ,
    const float* __restrict__ bias, float* __restrict__ outF,
    __half* __restrict__ hHi)
{
    extern __shared__ char sm[];
    const uint32_t smBase = smem_u32(sm);

    const int t = threadIdx.x;
    const int warp = t >> 5, lane = t & 31;
    const int wm = warp & 1, wn = warp >> 1;          // 2 x 4 warp grid

    const int nBase  = blockIdx.x * 128;
    const int aRow0  = blockIdx.y * 128 + blockIdx.z * AZ;
    const int bRow0  = blockIdx.z * BZ;

    float acc[4][4][4];
#pragma unroll
    for (int i = 0; i < 4; i++)
#pragma unroll
        for (int j = 0; j < 4; j++)
#pragma unroll
            for (int q = 0; q < 4; q++) acc[i][j][q] = 0.0f;

    // ---- per-thread load geometry ----
    const int rA = t >> 2, chA = t & 3;               // A rows rA, rA+64
    const int rB = t >> 4, chB = t & 15;              // B rows rB, rB+16
    const __half* pAh = Ahi + (size_t)(aRow0 + rA) * lda + chA * 8;
    const __half* pBh = Bhi + (size_t)(bRow0 + rB) * ldb + nBase + chB * 8;
    const uint32_t sA = smBase + rA * A_PITCH_B + chA * 16;
    const uint32_t sB = smBase + SZ_A + rB * B_PITCH_B + chB * 16;
    const size_t a64 = (size_t)64 * lda;
    const size_t b16 = (size_t)16 * ldb;

    auto load_tile = [&](int buf, int kt) {
        const size_t ka = (size_t)kt * 32;
        const size_t kb = (size_t)kt * 32 * ldb;
        const uint32_t ob = buf * BUF_STRIDE;
        cp16(sA + ob,                  pAh + ka);
        cp16(sA + ob + 64 * A_PITCH_B, pAh + ka + a64);
        cp16(sB + ob,                  pBh + kb);
        cp16(sB + ob + 16 * B_PITCH_B, pBh + kb + b16);
    };

    // per-lane ldmatrix address components
    const int aRowL  = lane & 15;
    const int aColB  = (lane >> 4) * 16;
    const int bRowL  = lane & 15;
    const int bColB  = (wn * 32 + (lane >> 4) * 8) * 2;

    const int ntiles = K / 32;
    load_tile(0, 0); CP_COMMIT();
    load_tile(1, 1); CP_COMMIT();

    int buf = 0;
    for (int kt = 0; kt < ntiles; kt++) {
        if (kt < ntiles - 1) { CP_WAIT(1); } else { CP_WAIT(0); }
        __syncthreads();

        if (kt + 2 < ntiles) {
            int nb = buf + 2; if (nb >= STAGES) nb -= STAGES;
            load_tile(nb, kt + 2);
            CP_COMMIT();
        }

        const uint32_t ob  = smBase + buf * BUF_STRIDE;
        const uint32_t obB = ob + SZ_A;

#pragma unroll
        for (int ks = 0; ks < 2; ks++) {
            uint32_t ahi[4][4];
#pragma unroll
            for (int mt = 0; mt < 4; mt++) {
                uint32_t ra = ob + (wm * 64 + mt * 16 + aRowL) * A_PITCH_B
                            + ks * 32 + aColB;
                LDSM4(ahi[mt][0], ahi[mt][1], ahi[mt][2], ahi[mt][3], ra);
            }
            uint32_t bhi[4][2];
#pragma unroll
            for (int bt = 0; bt < 2; bt++) {
                uint32_t rb = obB + (ks * 16 + bRowL) * B_PITCH_B + bColB + bt * 32;
                LDSM4T(bhi[bt*2][0], bhi[bt*2][1], bhi[bt*2+1][0], bhi[bt*2+1][1], rb);
            }
#pragma unroll
            for (int mt = 0; mt < 4; mt++)
#pragma unroll
                for (int nt = 0; nt < 4; nt++)
                    MMA(acc[mt][nt], ahi[mt], bhi[nt]);
        }
        buf++; if (buf >= STAGES) buf = 0;
    }

    // ---------------- epilogue ----------------
#pragma unroll
    for (int nt = 0; nt < 4; nt++) {
        int gCol = nBase + wn * 32 + nt * 8 + (lane & 3) * 2;
        float2 bv = make_float2(0.f, 0.f);
        if (MODE == 0) bv = *(const float2*)(bias + gCol);
#pragma unroll
        for (int mt = 0; mt < 4; mt++) {
            int gRow = aRow0 + wm * 64 + mt * 16 + (lane >> 2);
            if (MODE == 1) {
                *(float2*)(outF + (size_t)gRow * F_ + gCol) =
                    make_float2(acc[mt][nt][0], acc[mt][nt][1]);
                *(float2*)(outF + (size_t)(gRow + 8) * F_ + gCol) =
                    make_float2(acc[mt][nt][2], acc[mt][nt][3]);
            } else {
#pragma unroll
                for (int h = 0; h < 2; h++) {
                    __half2 vh;
                    vh.x = __float2half_rn(acc[mt][nt][h * 2]     + bv.x);
                    vh.y = __float2half_rn(acc[mt][nt][h * 2 + 1] + bv.y);
                    *(__half2*)(hHi + (size_t)(gRow + h * 8) * F_ + gCol) = vh;
                }
            }
        }
    }
}

// ---------------- cast_text: text -> fp16 (no other deps) ---------------------
__global__ __launch_bounds__(256) void cast_text(const float* __restrict__ x,
                                                 __half* __restrict__ hi) {
    size_t i = (size_t)blockIdx.x * 256 + threadIdx.x;   // one float4 each
    float4 v = ((const float4*)x)[i];
    __half2 a, b;
    a.x = __float2half_rn(v.x); a.y = __float2half_rn(v.y);
    b.x = __float2half_rn(v.z); b.y = __float2half_rn(v.w);
    __half2* ph = (__half2*)(hi + i * 4);
    ph[0] = a; ph[1] = b;
}

// ---------------- prep_all: W split + W@a_src/a_dst + bias dots ---------------
// blocks [0,256): split W to fp16.  [256,384): ws/wd rows.  384: bias dots.
__global__ __launch_bounds__(256) void prep_all(
    const float* __restrict__ W, const float* __restrict__ bias,
    const float* __restrict__ a_src, const float* __restrict__ a_dst,
    __half* __restrict__ WHi, float* __restrict__ ws, float* __restrict__ wd,
    float* __restrict__ sbdb)
{
    int bid = blockIdx.x;
    int t = threadIdx.x;
    if (bid < 256) {
        size_t i = (size_t)bid * 256 + t;           // float4 index into W
        float4 v = ((const float4*)W)[i];
        __half2 a, b;
        a.x = __float2half_rn(v.x); a.y = __float2half_rn(v.y);
        b.x = __float2half_rn(v.z); b.y = __float2half_rn(v.w);
        __half2* ph = (__half2*)(WHi + i * 4);
        ph[0] = a; ph[1] = b;
    } else if (bid < 384) {
        if (t < 128) {
            int row = (bid - 256) * 4 + (t >> 5);
            int lane = t & 31;
            const float4* wr = (const float4*)(W + (size_t)row * F_);
            const float4* as = (const float4*)a_src;
            const float4* ad = (const float4*)a_dst;
            float s = 0.f, d = 0.f;
#pragma unroll
            for (int i = lane; i < F_ / 4; i += 32) {
                float4 w = wr[i], a = as[i], b = ad[i];
                s += w.x * a.x + w.y * a.y + w.z * a.z + w.w * a.w;
                d += w.x * b.x + w.y * b.y + w.z * b.z + w.w * b.w;
            }
#pragma unroll
            for (int o = 16; o; o >>= 1) {
                s += __shfl_xor_sync(FULLM, s, o);
                d += __shfl_xor_sync(FULLM, d, o);
            }
            if (lane == 0) { ws[row] = s; wd[row] = d; }
        }
    } else {
        if (t < 128) {
            const float4* bb = (const float4*)bias;
            const float4* as = (const float4*)a_src;
            const float4* ad = (const float4*)a_dst;
            float4 v = bb[t], a = as[t], c = ad[t];
            float s = v.x * a.x + v.y * a.y + v.z * a.z + v.w * a.w;
            float d = v.x * c.x + v.y * c.y + v.z * c.z + v.w * c.w;
#pragma unroll
            for (int o = 16; o; o >>= 1) {
                s += __shfl_xor_sync(FULLM, s, o);
                d += __shfl_xor_sync(FULLM, d, o);
            }
            __shared__ float rs[4], rd[4];
            int lane = t & 31, wid = t >> 5;
            if (lane == 0) { rs[wid] = s; rd[wid] = d; }
            __syncthreads();
            if (t == 0) {
                sbdb[0] = rs[0] + rs[1] + rs[2] + rs[3];
                sbdb[1] = rd[0] + rd[1] + rd[2] + rd[3];
            }
        }
    }
}

// ---------------- sd_only: s/d per node (text re-read; L2-resident) -----------
__global__ __launch_bounds__(128) void sd_only(
    const float* __restrict__ text, const float* __restrict__ ws,
    const float* __restrict__ wd, const float* __restrict__ sbdb,
    float* __restrict__ s, float* __restrict__ d)
{
    int row = blockIdx.x;
    int t = threadIdx.x;                         // one float4 per thread
    float4 x = ((const float4*)(text + (size_t)row * F_))[t];
    float4 a = ((const float4*)ws)[t];
    float4 c = ((const float4*)wd)[t];
    float ss = x.x * a.x + x.y * a.y + x.z * a.z + x.w * a.w;
    float dd = x.x * c.x + x.y * c.y + x.z * c.z + x.w * c.w;
#pragma unroll
    for (int o = 16; o; o >>= 1) {
        ss += __shfl_xor_sync(FULLM, ss, o);
        dd += __shfl_xor_sync(FULLM, dd, o);
    }
    __shared__ float rs[4], rd[4];
    int lane = t & 31, wid = t >> 5;
    if (lane == 0) { rs[wid] = ss; rd[wid] = dd; }
    __syncthreads();
    if (t == 0) {
        s[row] = rs[0] + rs[1] + rs[2] + rs[3] + sbdb[0];
        d[row] = rd[0] + rd[1] + rd[2] + rd[3] + sbdb[1];
    }
}

// ---------------- softmax probabilities -> fp16 (hi only) ---------------------
__global__ __launch_bounds__(256) void prob_kernel(
    const int* __restrict__ adj, const float* __restrict__ s,
    const float* __restrict__ dvec, __half* __restrict__ Phi)
{
    int row = blockIdx.x;
    int t = threadIdx.x;
    const int j0 = t * 8;
    const int4* arow = (const int4*)(adj + (size_t)row * N_ + j0);
    const float4* drow = (const float4*)(dvec + ((row >> 11) << 11) + j0);
    float si = s[row];

    int4 a0 = arow[0], a1 = arow[1];
    float4 d0 = drow[0], d1 = drow[1];
    int am[8] = {a0.x, a0.y, a0.z, a0.w, a1.x, a1.y, a1.z, a1.w};
    float dv[8] = {d0.x, d0.y, d0.z, d0.w, d1.x, d1.y, d1.z, d1.w};

    float sc[8];
#pragma unroll
    for (int q = 0; q < 8; q++) {
        float x = si + dv[q];
        x = (x >= 0.0f) ? x : SLOPE * x;
        sc[q] = am[q] ? NEGV : x;
    }

    __shared__ float redA[8], redB[8];
    int lane = t & 31, wid = t >> 5;
    float m = sc[0];
#pragma unroll
    for (int q = 1; q < 8; q++) m = fmaxf(m, sc[q]);
#pragma unroll
    for (int o = 16; o; o >>= 1) m = fmaxf(m, __shfl_xor_sync(FULLM, m, o));
    if (lane == 0) redA[wid] = m;
    __syncthreads();
    if (wid == 0) {
        float v = (lane < 8) ? redA[lane] : -3.4e38f;
#pragma unroll
        for (int o = 16; o; o >>= 1) v = fmaxf(v, __shfl_xor_sync(FULLM, v, o));
        if (lane == 0) redA[0] = v;
    }
    __syncthreads();
    m = redA[0];

    float l = 0.0f;
#pragma unroll
    for (int q = 0; q < 8; q++) { sc[q] = __expf(sc[q] - m); l += sc[q]; }
#pragma unroll
    for (int o = 16; o; o >>= 1) l += __shfl_xor_sync(FULLM, l, o);
    if (lane == 0) redB[wid] = l;
    __syncthreads();
    if (wid == 0) {
        float v = (lane < 8) ? redB[lane] : 0.0f;
#pragma unroll
        for (int o = 16; o; o >>= 1) v += __shfl_xor_sync(FULLM, v, o);
        if (lane == 0) redB[0] = v;
    }
    __syncthreads();
    float inv = 1.0f / redB[0];

    __half2 w[4];
#pragma unroll
    for (int q = 0; q < 4; q++) {
        w[q].x = __float2half_rn(sc[q * 2] * inv);
        w[q].y = __float2half_rn(sc[q * 2 + 1] * inv);
    }
    *(uint4*)(Phi + (size_t)row * N_ + j0) = *(uint4*)w;
}

// ---------------- launch -------------------------------------------------------
extern "C" void kernel_launch(void* const* d_in, const int* in_sizes, int n_in,
                              void* d_out, int out_size) {
    (void)in_sizes; (void)n_in; (void)out_size;
    const float* text  = (const float*)d_in[0];
    const int*   adj   = (const int*)d_in[1];
    const float* W     = (const float*)d_in[2];
    const float* bias  = (const float*)d_in[3];
    const float* a_src = (const float*)d_in[4];
    const float* a_dst = (const float*)d_in[5];
    float* out = (float*)d_out;

    __half *tHi, *WHi, *hHi, *PHi;
    float *ws, *wd, *sbdb, *sv, *dv;
    cudaGetSymbolAddress((void**)&tHi,  g_tHi);
    cudaGetSymbolAddress((void**)&WHi,  g_WHi);
    cudaGetSymbolAddress((void**)&hHi,  g_hHi);
    cudaGetSymbolAddress((void**)&ws,   g_ws);
    cudaGetSymbolAddress((void**)&wd,   g_wd);
    cudaGetSymbolAddress((void**)&sbdb, g_sbdb);
    cudaGetSymbolAddress((void**)&sv,   g_sv);
    cudaGetSymbolAddress((void**)&dv,   g_dv);
    cudaGetSymbolAddress((void**)&PHi,  g_PHi);

    // one-time setup (first call runs uncaptured; resources reused in capture)
    static cudaStream_t s1 = nullptr;
    static cudaEvent_t evFork = nullptr, evCast = nullptr, evPrep = nullptr,
                       evK1 = nullptr;
    static int init_done = 0;
    if (!init_done) {
        cudaFuncSetAttribute(gemm_mma<0>,
                             cudaFuncAttributeMaxDynamicSharedMemorySize, SMEM_BYTES);
        cudaFuncSetAttribute(gemm_mma<1>,
                             cudaFuncAttributeMaxDynamicSharedMemorySize, SMEM_BYTES);
        cudaStreamCreateWithFlags(&s1, cudaStreamNonBlocking);
        cudaEventCreateWithFlags(&evFork, cudaEventDisableTiming);
        cudaEventCreateWithFlags(&evCast, cudaEventDisableTiming);
        cudaEventCreateWithFlags(&evPrep, cudaEventDisableTiming);
        cudaEventCreateWithFlags(&evK1,   cudaEventDisableTiming);
        init_done = 1;
    }

    // LEGAL fork: s1 must wait on an origin-stream event BEFORE any s1 work.
    cudaEventRecord(evFork, 0);
    cudaStreamWaitEvent(s1, evFork, 0);

    // s1: W cast + score-vector preps (concurrent with cast_text on s0)
    prep_all<<<385, 256, 0, s1>>>(W, bias, a_src, a_dst, WHi, ws, wd, sbdb);
    cudaEventRecord(evPrep, s1);

    // s0: cast text -> fp16 (no deps; warms text into L2)
    cast_text<<<(MTOT * F_ / 4) / 256, 256>>>(text, tHi);
    cudaEventRecord(evCast, 0);

    // s1: K1 gemm — needs tHi (evCast) + WHi (in-stream order)
    cudaStreamWaitEvent(s1, evCast, 0);
    gemm_mma<0><<<dim3(F_ / 128, MTOT / 128, 1), 256, SMEM_BYTES, s1>>>(
        tHi, WHi, F_, F_, F_, 0, 0, bias, nullptr, hHi);
    cudaEventRecord(evK1, s1);

    // s0: s/d per node — needs ws/wd/sbdb (evPrep); text now L2-resident
    cudaStreamWaitEvent(0, evPrep, 0);
    sd_only<<<MTOT, 128>>>(text, ws, wd, sbdb, sv, dv);

    // s0: softmax probabilities (overlaps with K1 on s1)
    prob_kernel<<<MTOT, 256>>>(adj, sv, dv, PHi);

    // s0: K4 — needs PHi (in-stream) + hHi (evK1)
    cudaStreamWaitEvent(0, evK1, 0);
    gemm_mma<1><<<dim3(F_ / 128, N_ / 128, B_), 256, SMEM_BYTES>>>(
        PHi, hHi, N_, F_, N_, N_, N_, nullptr, out, nullptr);
}

// round 12
// speedup vs baseline: 1.0816x; 1.0816x over previous
#include <cuda_runtime.h>
#include <cuda_fp16.h>
#include <cstdint>

#define B_    8
#define N_    2048
#define F_    512
#define MTOT  (B_ * N_)          // 16384
#define HALF_ROWS (MTOT / 2)     // 8192 (4 batches)
#define NEGV  (-10000.0f)
#define SLOPE 0.2f
#define FULLM 0xFFFFFFFFu

// ---------------- device scratch (sanctioned static-array path) -------------
__device__ __half g_tHi[(size_t)MTOT * F_];
__device__ __half g_WHi[(size_t)F_ * F_];
__device__ __half g_hHi[(size_t)MTOT * F_];   // hidden fp16, row-major
__device__ float g_ws[F_], g_wd[F_];          // W @ a_src, W @ a_dst
__device__ float g_sbdb[2];                   // b.a_src, b.a_dst
__device__ float g_sv[MTOT], g_dv[MTOT];
__device__ __half g_PHi[(size_t)MTOT * N_];

// ---------------- base-target PTX helpers ------------------------------------
__device__ __forceinline__ uint32_t smem_u32(const void* p) {
    uint32_t a;
    asm("{ .reg .u64 t; cvta.to.shared.u64 t, %1; cvt.u32.u64 %0, t; }"
        : "=r"(a) : "l"(p));
    return a;
}
__device__ __forceinline__ void cp16(uint32_t dst, const void* src) {
    asm volatile("cp.async.cg.shared.global [%0], [%1], 16;" :: "r"(dst), "l"(src));
}
#define CP_COMMIT() asm volatile("cp.async.commit_group;" ::: "memory")
#define CP_WAIT(n)  asm volatile("cp.async.wait_group %0;" :: "n"(n) : "memory")

#define LDSM4(r0, r1, r2, r3, addr) \
    asm volatile("ldmatrix.sync.aligned.m8n8.x4.shared.b16 {%0,%1,%2,%3}, [%4];" \
                 : "=r"(r0), "=r"(r1), "=r"(r2), "=r"(r3) : "r"(addr))
#define LDSM4T(r0, r1, r2, r3, addr) \
    asm volatile("ldmatrix.sync.aligned.m8n8.x4.trans.shared.b16 {%0,%1,%2,%3}, [%4];" \
                 : "=r"(r0), "=r"(r1), "=r"(r2), "=r"(r3) : "r"(addr))

#define MMA(d, a, b) \
    asm volatile("mma.sync.aligned.m16n8k16.row.col.f32.f16.f16.f32 " \
                 "{%0,%1,%2,%3}, {%4,%5,%6,%7}, {%8,%9}, {%0,%1,%2,%3};" \
                 : "+f"((d)[0]), "+f"((d)[1]), "+f"((d)[2]), "+f"((d)[3]) \
                 : "r"((a)[0]), "r"((a)[1]), "r"((a)[2]), "r"((a)[3]), \
                   "r"((b)[0]), "r"((b)[1]))

// ---------------- SMEM layout -------------------------------------------------
#define A_PITCH_B 80
#define B_PITCH_B 272
#define SZ_A (128 * A_PITCH_B)            // 10240
#define SZ_B (32 * B_PITCH_B)             // 8704
#define STAGES 3
#define BUF_STRIDE (SZ_A + SZ_B)          // 18944
#define SMEM_BYTES (STAGES * BUF_STRIDE)  // 56832

// ---------------- 1-term fp16 GEMM (mma.sync), CTA 128x128x32 ----------------
// EXACT R7 kernel text (known-good codegen; do not refactor).
// C = Ahi * Bhi  (fp32 accumulate)
// MODE 0: hHi = fp16(C + bias)
// MODE 1: outF[row][512] = C  (fp32)
template<int MODE>
__global__ __launch_bounds__(256) void gemm_mma(
    const __half* __restrict__ Ahi, const __half* __restrict__ Bhi,
    int lda, int ldb, int K, int AZ, int BZ,
    const float* __restrict__ bias, float* __restrict__ outF,
    __half* __restrict__ hHi)
{
    extern __shared__ char sm[];
    const uint32_t smBase = smem_u32(sm);

    const int t = threadIdx.x;
    const int warp = t >> 5, lane = t & 31;
    const int wm = warp & 1, wn = warp >> 1;          // 2 x 4 warp grid

    const int nBase  = blockIdx.x * 128;
    const int aRow0  = blockIdx.y * 128 + blockIdx.z * AZ;
    const int bRow0  = blockIdx.z * BZ;

    float acc[4][4][4];
#pragma unroll
    for (int i = 0; i < 4; i++)
#pragma unroll
        for (int j = 0; j < 4; j++)
#pragma unroll
            for (int q = 0; q < 4; q++) acc[i][j][q] = 0.0f;

    // ---- per-thread load geometry ----
    const int rA = t >> 2, chA = t & 3;               // A rows rA, rA+64
    const int rB = t >> 4, chB = t & 15;              // B rows rB, rB+16
    const __half* pAh = Ahi + (size_t)(aRow0 + rA) * lda + chA * 8;
    const __half* pBh = Bhi + (size_t)(bRow0 + rB) * ldb + nBase + chB * 8;
    const uint32_t sA = smBase + rA * A_PITCH_B + chA * 16;
    const uint32_t sB = smBase + SZ_A + rB * B_PITCH_B + chB * 16;
    const size_t a64 = (size_t)64 * lda;
    const size_t b16 = (size_t)16 * ldb;

    auto load_tile = [&](int buf, int kt) {
        const size_t ka = (size_t)kt * 32;
        const size_t kb = (size_t)kt * 32 * ldb;
        const uint32_t ob = buf * BUF_STRIDE;
        cp16(sA + ob,                  pAh + ka);
        cp16(sA + ob + 64 * A_PITCH_B, pAh + ka + a64);
        cp16(sB + ob,                  pBh + kb);
        cp16(sB + ob + 16 * B_PITCH_B, pBh + kb + b16);
    };

    // per-lane ldmatrix address components
    const int aRowL  = lane & 15;
    const int aColB  = (lane >> 4) * 16;
    const int bRowL  = lane & 15;
    const int bColB  = (wn * 32 + (lane >> 4) * 8) * 2;

    const int ntiles = K / 32;
    load_tile(0, 0); CP_COMMIT();
    load_tile(1, 1); CP_COMMIT();

    int buf = 0;
    for (int kt = 0; kt < ntiles; kt++) {
        if (kt < ntiles - 1) { CP_WAIT(1); } else { CP_WAIT(0); }
        __syncthreads();

        if (kt + 2 < ntiles) {
            int nb = buf + 2; if (nb >= STAGES) nb -= STAGES;
            load_tile(nb, kt + 2);
            CP_COMMIT();
        }

        const uint32_t ob  = smBase + buf * BUF_STRIDE;
        const uint32_t obB = ob + SZ_A;

#pragma unroll
        for (int ks = 0; ks < 2; ks++) {
            uint32_t ahi[4][4];
#pragma unroll
            for (int mt = 0; mt < 4; mt++) {
                uint32_t ra = ob + (wm * 64 + mt * 16 + aRowL) * A_PITCH_B
                            + ks * 32 + aColB;
                LDSM4(ahi[mt][0], ahi[mt][1], ahi[mt][2], ahi[mt][3], ra);
            }
            uint32_t bhi[4][2];
#pragma unroll
            for (int bt = 0; bt < 2; bt++) {
                uint32_t rb = obB + (ks * 16 + bRowL) * B_PITCH_B + bColB + bt * 32;
                LDSM4T(bhi[bt*2][0], bhi[bt*2][1], bhi[bt*2+1][0], bhi[bt*2+1][1], rb);
            }
#pragma unroll
            for (int mt = 0; mt < 4; mt++)
#pragma unroll
                for (int nt = 0; nt < 4; nt++)
                    MMA(acc[mt][nt], ahi[mt], bhi[nt]);
        }
        buf++; if (buf >= STAGES) buf = 0;
    }

    // ---------------- epilogue ----------------
#pragma unroll
    for (int nt = 0; nt < 4; nt++) {
        int gCol = nBase + wn * 32 + nt * 8 + (lane & 3) * 2;
        float2 bv = make_float2(0.f, 0.f);
        if (MODE == 0) bv = *(const float2*)(bias + gCol);
#pragma unroll
        for (int mt = 0; mt < 4; mt++) {
            int gRow = aRow0 + wm * 64 + mt * 16 + (lane >> 2);
            if (MODE == 1) {
                *(float2*)(outF + (size_t)gRow * F_ + gCol) =
                    make_float2(acc[mt][nt][0], acc[mt][nt][1]);
                *(float2*)(outF + (size_t)(gRow + 8) * F_ + gCol) =
                    make_float2(acc[mt][nt][2], acc[mt][nt][3]);
            } else {
#pragma unroll
                for (int h = 0; h < 2; h++) {
                    __half2 vh;
                    vh.x = __float2half_rn(acc[mt][nt][h * 2]     + bv.x);
                    vh.y = __float2half_rn(acc[mt][nt][h * 2 + 1] + bv.y);
                    *(__half2*)(hHi + (size_t)(gRow + h * 8) * F_ + gCol) = vh;
                }
            }
        }
    }
}

// ---------------- prep_all: W split + W@a_src/a_dst + bias dots ---------------
// blocks [0,256): split W to fp16.  [256,384): ws/wd rows.  384: bias dots.
__global__ __launch_bounds__(256) void prep_all(
    const float* __restrict__ W, const float* __restrict__ bias,
    const float* __restrict__ a_src, const float* __restrict__ a_dst,
    __half* __restrict__ WHi, float* __restrict__ ws, float* __restrict__ wd,
    float* __restrict__ sbdb)
{
    int bid = blockIdx.x;
    int t = threadIdx.x;
    if (bid < 256) {
        size_t i = (size_t)bid * 256 + t;           // float4 index into W
        float4 v = ((const float4*)W)[i];
        __half2 a, b;
        a.x = __float2half_rn(v.x); a.y = __float2half_rn(v.y);
        b.x = __float2half_rn(v.z); b.y = __float2half_rn(v.w);
        __half2* ph = (__half2*)(WHi + i * 4);
        ph[0] = a; ph[1] = b;
    } else if (bid < 384) {
        if (t < 128) {
            int row = (bid - 256) * 4 + (t >> 5);
            int lane = t & 31;
            const float4* wr = (const float4*)(W + (size_t)row * F_);
            const float4* as = (const float4*)a_src;
            const float4* ad = (const float4*)a_dst;
            float s = 0.f, d = 0.f;
#pragma unroll
            for (int i = lane; i < F_ / 4; i += 32) {
                float4 w = wr[i], a = as[i], b = ad[i];
                s += w.x * a.x + w.y * a.y + w.z * a.z + w.w * a.w;
                d += w.x * b.x + w.y * b.y + w.z * b.z + w.w * b.w;
            }
#pragma unroll
            for (int o = 16; o; o >>= 1) {
                s += __shfl_xor_sync(FULLM, s, o);
                d += __shfl_xor_sync(FULLM, d, o);
            }
            if (lane == 0) { ws[row] = s; wd[row] = d; }
        }
    } else {
        if (t < 128) {
            const float4* bb = (const float4*)bias;
            const float4* as = (const float4*)a_src;
            const float4* ad = (const float4*)a_dst;
            float4 v = bb[t], a = as[t], c = ad[t];
            float s = v.x * a.x + v.y * a.y + v.z * a.z + v.w * a.w;
            float d = v.x * c.x + v.y * c.y + v.z * c.z + v.w * c.w;
#pragma unroll
            for (int o = 16; o; o >>= 1) {
                s += __shfl_xor_sync(FULLM, s, o);
                d += __shfl_xor_sync(FULLM, d, o);
            }
            __shared__ float rs[4], rd[4];
            int lane = t & 31, wid = t >> 5;
            if (lane == 0) { rs[wid] = s; rd[wid] = d; }
            __syncthreads();
            if (t == 0) {
                sbdb[0] = rs[0] + rs[1] + rs[2] + rs[3];
                sbdb[1] = rd[0] + rd[1] + rd[2] + rd[3];
            }
        }
    }
}

// ---------------- split_sd: text -> tHi (fp16) + s/d per node (fused) ---------
__global__ __launch_bounds__(128) void split_sd(
    const float* __restrict__ text, const float* __restrict__ ws,
    const float* __restrict__ wd, const float* __restrict__ sbdb,
    __half* __restrict__ tHi, float* __restrict__ s, float* __restrict__ d)
{
    int row = blockIdx.x;
    int t = threadIdx.x;                         // one float4 per thread
    float4 x = ((const float4*)(text + (size_t)row * F_))[t];

    __half2 h0, h1;
    h0.x = __float2half_rn(x.x); h0.y = __float2half_rn(x.y);
    h1.x = __float2half_rn(x.z); h1.y = __float2half_rn(x.w);
    __half2* ph = (__half2*)(tHi + (size_t)row * F_) + t * 2;
    ph[0] = h0; ph[1] = h1;

    float4 a = ((const float4*)ws)[t];
    float4 c = ((const float4*)wd)[t];
    float ss = x.x * a.x + x.y * a.y + x.z * a.z + x.w * a.w;
    float dd = x.x * c.x + x.y * c.y + x.z * c.z + x.w * c.w;
#pragma unroll
    for (int o = 16; o; o >>= 1) {
        ss += __shfl_xor_sync(FULLM, ss, o);
        dd += __shfl_xor_sync(FULLM, dd, o);
    }
    __shared__ float rs[4], rd[4];
    int lane = t & 31, wid = t >> 5;
    if (lane == 0) { rs[wid] = ss; rd[wid] = dd; }
    __syncthreads();
    if (t == 0) {
        s[row] = rs[0] + rs[1] + rs[2] + rs[3] + sbdb[0];
        d[row] = rd[0] + rd[1] + rd[2] + rd[3] + sbdb[1];
    }
}

// ---------------- softmax probabilities -> fp16 (hi only) ---------------------
__global__ __launch_bounds__(256) void prob_kernel(
    const int* __restrict__ adj, const float* __restrict__ s,
    const float* __restrict__ dvec, __half* __restrict__ Phi, int rowOff)
{
    int row = blockIdx.x + rowOff;
    int t = threadIdx.x;
    const int j0 = t * 8;
    const int4* arow = (const int4*)(adj + (size_t)row * N_ + j0);
    const float4* drow = (const float4*)(dvec + ((row >> 11) << 11) + j0);
    float si = s[row];

    int4 a0 = arow[0], a1 = arow[1];
    float4 d0 = drow[0], d1 = drow[1];
    int am[8] = {a0.x, a0.y, a0.z, a0.w, a1.x, a1.y, a1.z, a1.w};
    float dv[8] = {d0.x, d0.y, d0.z, d0.w, d1.x, d1.y, d1.z, d1.w};

    float sc[8];
#pragma unroll
    for (int q = 0; q < 8; q++) {
        float x = si + dv[q];
        x = (x >= 0.0f) ? x : SLOPE * x;
        sc[q] = am[q] ? NEGV : x;
    }

    __shared__ float redA[8], redB[8];
    int lane = t & 31, wid = t >> 5;
    float m = sc[0];
#pragma unroll
    for (int q = 1; q < 8; q++) m = fmaxf(m, sc[q]);
#pragma unroll
    for (int o = 16; o; o >>= 1) m = fmaxf(m, __shfl_xor_sync(FULLM, m, o));
    if (lane == 0) redA[wid] = m;
    __syncthreads();
    if (wid == 0) {
        float v = (lane < 8) ? redA[lane] : -3.4e38f;
#pragma unroll
        for (int o = 16; o; o >>= 1) v = fmaxf(v, __shfl_xor_sync(FULLM, v, o));
        if (lane == 0) redA[0] = v;
    }
    __syncthreads();
    m = redA[0];

    float l = 0.0f;
#pragma unroll
    for (int q = 0; q < 8; q++) { sc[q] = __expf(sc[q] - m); l += sc[q]; }
#pragma unroll
    for (int o = 16; o; o >>= 1) l += __shfl_xor_sync(FULLM, l, o);
    if (lane == 0) redB[wid] = l;
    __syncthreads();
    if (wid == 0) {
        float v = (lane < 8) ? redB[lane] : 0.0f;
#pragma unroll
        for (int o = 16; o; o >>= 1) v += __shfl_xor_sync(FULLM, v, o);
        if (lane == 0) redB[0] = v;
    }
    __syncthreads();
    float inv = 1.0f / redB[0];

    __half2 w[4];
#pragma unroll
    for (int q = 0; q < 4; q++) {
        w[q].x = __float2half_rn(sc[q * 2] * inv);
        w[q].y = __float2half_rn(sc[q * 2 + 1] * inv);
    }
    *(uint4*)(Phi + (size_t)row * N_ + j0) = *(uint4*)w;
}

// ---------------- launch -------------------------------------------------------
extern "C" void kernel_launch(void* const* d_in, const int* in_sizes, int n_in,
                              void* d_out, int out_size) {
    (void)in_sizes; (void)n_in; (void)out_size;
    const float* text  = (const float*)d_in[0];
    const int*   adj   = (const int*)d_in[1];
    const float* W     = (const float*)d_in[2];
    const float* bias  = (const float*)d_in[3];
    const float* a_src = (const float*)d_in[4];
    const float* a_dst = (const float*)d_in[5];
    float* out = (float*)d_out;

    __half *tHi, *WHi, *hHi, *PHi;
    float *ws, *wd, *sbdb, *sv, *dv;
    cudaGetSymbolAddress((void**)&tHi,  g_tHi);
    cudaGetSymbolAddress((void**)&WHi,  g_WHi);
    cudaGetSymbolAddress((void**)&hHi,  g_hHi);
    cudaGetSymbolAddress((void**)&ws,   g_ws);
    cudaGetSymbolAddress((void**)&wd,   g_wd);
    cudaGetSymbolAddress((void**)&sbdb, g_sbdb);
    cudaGetSymbolAddress((void**)&sv,   g_sv);
    cudaGetSymbolAddress((void**)&dv,   g_dv);
    cudaGetSymbolAddress((void**)&PHi,  g_PHi);

    // one-time setup (first call runs uncaptured; resources reused in capture)
    static cudaStream_t s1 = nullptr;
    static cudaEvent_t evSD = nullptr, evK1a = nullptr, evP1 = nullptr;
    static int init_done = 0;
    if (!init_done) {
        cudaFuncSetAttribute(gemm_mma<0>,
                             cudaFuncAttributeMaxDynamicSharedMemorySize, SMEM_BYTES);
        cudaFuncSetAttribute(gemm_mma<1>,
                             cudaFuncAttributeMaxDynamicSharedMemorySize, SMEM_BYTES);
        cudaStreamCreateWithFlags(&s1, cudaStreamNonBlocking);
        cudaEventCreateWithFlags(&evSD,  cudaEventDisableTiming);
        cudaEventCreateWithFlags(&evK1a, cudaEventDisableTiming);
        cudaEventCreateWithFlags(&evP1,  cudaEventDisableTiming);
        init_done = 1;
    }

    const size_t hOff = (size_t)HALF_ROWS * F_;   // half offset in hidden/text/out
    const size_t pOff = (size_t)HALF_ROWS * N_;   // half offset in P

    // s0: preps + fused text cast + s/d (R9 structure)
    prep_all<<<385, 256>>>(W, bias, a_src, a_dst, WHi, ws, wd, sbdb);
    split_sd<<<MTOT, 128>>>(text, ws, wd, sbdb, tHi, sv, dv);
    cudaEventRecord(evSD, 0);

    // s1 (fork via evSD — first s1 op is the wait): K1 halves, then prob_g1
    cudaStreamWaitEvent(s1, evSD, 0);
    gemm_mma<0><<<dim3(F_ / 128, HALF_ROWS / 128, 1), 256, SMEM_BYTES, s1>>>(
        tHi, WHi, F_, F_, F_, 0, 0, bias, nullptr, hHi);
    cudaEventRecord(evK1a, s1);
    gemm_mma<0><<<dim3(F_ / 128, HALF_ROWS / 128, 1), 256, SMEM_BYTES, s1>>>(
        tHi + hOff, WHi, F_, F_, F_, 0, 0, bias, nullptr, hHi + hOff);
    prob_kernel<<<HALF_ROWS, 256, 0, s1>>>(adj, sv, dv, PHi, HALF_ROWS);
    cudaEventRecord(evP1, s1);

    // s0: prob_g0 (overlaps K1 on s1)
    prob_kernel<<<HALF_ROWS, 256>>>(adj, sv, dv, PHi, 0);

    // s0: K4 group 0 (batches 0-3) — needs PHi g0 (in-stream) + hHi g0 (evK1a)
    cudaStreamWaitEvent(0, evK1a, 0);
    gemm_mma<1><<<dim3(F_ / 128, N_ / 128, B_ / 2), 256, SMEM_BYTES>>>(
        PHi, hHi, N_, F_, N_, N_, N_, nullptr, out, nullptr);

    // s0: K4 group 1 (batches 4-7) — needs prob_g1 + K1_g1 (both ≤ evP1)
    cudaStreamWaitEvent(0, evP1, 0);
    gemm_mma<1><<<dim3(F_ / 128, N_ / 128, B_ / 2), 256, SMEM_BYTES>>>(
        PHi + pOff, hHi + hOff, N_, F_, N_, N_, N_, nullptr, out + hOff, nullptr);
}